// round 1
// baseline (speedup 1.0000x reference)
#include <cuda_runtime.h>
#include <math.h>

#define BATCH   8
#define OUT_LEN 1024
#define IN_LEN  4096
#define HDIM    256
#define NROWS   (BATCH * OUT_LEN)

// Scratch (allocation-free rule: __device__ globals)
__device__ float g_rowmax[NROWS];
__device__ float g_rowsum[NROWS];

__device__ __forceinline__ void atomicMaxFloat(float* addr, float val) {
    if (val >= 0.0f) atomicMax((int*)addr, __float_as_int(val));
    else             atomicMin((unsigned int*)addr, __float_as_uint(val));
}

__global__ void init_rowmax_kernel() {
    int i = blockIdx.x * blockDim.x + threadIdx.x;
    if (i < NROWS) g_rowmax[i] = -INFINITY;
}

// ---------------------------------------------------------------------------
// GEMM1: scores[b,o,i] = sum_h Q[b,o,h] * K[b,i,h]  (A @ B^T, both K-major)
// 128x128 tile, BK=16, 256 threads, 8x8 per thread.
// Epilogue: mask (i >= len -> -inf), write raw scores, atomic row-max.
// ---------------------------------------------------------------------------
__global__ __launch_bounds__(256) void score_kernel(
    const float* __restrict__ Q, const float* __restrict__ Kenc,
    const int* __restrict__ lengths, float* __restrict__ attn)
{
    int b  = blockIdx.z;
    int m0 = blockIdx.y * 128;   // out rows
    int n0 = blockIdx.x * 128;   // in cols
    const float* A  = Q    + (size_t)b * OUT_LEN * HDIM;
    const float* Bm = Kenc + (size_t)b * IN_LEN  * HDIM;
    int len = lengths[b];

    __shared__ float As[16][128];
    __shared__ float Bs[16][128];

    int tid = threadIdx.x;
    int tx = tid & 15, ty = tid >> 4;

    float acc[8][8] = {};

    for (int k0 = 0; k0 < HDIM; k0 += 16) {
#pragma unroll
        for (int s = 0; s < 2; s++) {
            int f   = tid + s * 256;     // float4 index (512 per tile)
            int row = f >> 2;            // 0..127
            int kq  = (f & 3) << 2;      // 0,4,8,12
            float4 v = *reinterpret_cast<const float4*>(&A [(size_t)(m0 + row) * HDIM + k0 + kq]);
            As[kq + 0][row] = v.x; As[kq + 1][row] = v.y;
            As[kq + 2][row] = v.z; As[kq + 3][row] = v.w;
            float4 w = *reinterpret_cast<const float4*>(&Bm[(size_t)(n0 + row) * HDIM + k0 + kq]);
            Bs[kq + 0][row] = w.x; Bs[kq + 1][row] = w.y;
            Bs[kq + 2][row] = w.z; Bs[kq + 3][row] = w.w;
        }
        __syncthreads();
#pragma unroll
        for (int kk = 0; kk < 16; kk++) {
            float a[8], bb[8];
            *(float4*)&a[0]  = *(float4*)&As[kk][ty * 8];
            *(float4*)&a[4]  = *(float4*)&As[kk][ty * 8 + 4];
            *(float4*)&bb[0] = *(float4*)&Bs[kk][tx * 8];
            *(float4*)&bb[4] = *(float4*)&Bs[kk][tx * 8 + 4];
#pragma unroll
            for (int i = 0; i < 8; i++)
#pragma unroll
                for (int j = 0; j < 8; j++)
                    acc[i][j] = fmaf(a[i], bb[j], acc[i][j]);
        }
        __syncthreads();
    }

    float* outbase = attn + (size_t)b * OUT_LEN * IN_LEN;
#pragma unroll
    for (int i = 0; i < 8; i++) {
        int m = m0 + ty * 8 + i;
        float rmax = -INFINITY;
#pragma unroll
        for (int j = 0; j < 8; j++) {
            int n = n0 + tx * 8 + j;
            float c = (n < len) ? acc[i][j] : -INFINITY;
            acc[i][j] = c;
            rmax = fmaxf(rmax, c);
        }
        float4* dst = (float4*)&outbase[(size_t)m * IN_LEN + n0 + tx * 8];
        dst[0] = make_float4(acc[i][0], acc[i][1], acc[i][2], acc[i][3]);
        dst[1] = make_float4(acc[i][4], acc[i][5], acc[i][6], acc[i][7]);
        // reduce across the 16 lanes sharing this row (tx group stays in half-warp)
#pragma unroll
        for (int off = 8; off > 0; off >>= 1)
            rmax = fmaxf(rmax, __shfl_xor_sync(0xffffffffu, rmax, off));
        if (tx == 0) atomicMaxFloat(&g_rowmax[b * OUT_LEN + m], rmax);
    }
}

// ---------------------------------------------------------------------------
// Per-row sum of exp(s - max). One block per row.
// ---------------------------------------------------------------------------
__global__ __launch_bounds__(256) void rowsum_kernel(const float* __restrict__ attn)
{
    int row = blockIdx.x;
    const float4* s = (const float4*)(attn + (size_t)row * IN_LEN);
    float m = g_rowmax[row];
    float sum = 0.0f;
    for (int i = threadIdx.x; i < IN_LEN / 4; i += 256) {
        float4 v = s[i];
        sum += __expf(v.x - m) + __expf(v.y - m) + __expf(v.z - m) + __expf(v.w - m);
    }
#pragma unroll
    for (int off = 16; off > 0; off >>= 1)
        sum += __shfl_xor_sync(0xffffffffu, sum, off);
    __shared__ float red[8];
    if ((threadIdx.x & 31) == 0) red[threadIdx.x >> 5] = sum;
    __syncthreads();
    if (threadIdx.x == 0) {
        float t = 0.0f;
#pragma unroll
        for (int i = 0; i < 8; i++) t += red[i];
        g_rowsum[row] = t;
    }
}

// ---------------------------------------------------------------------------
// In-place normalize: attn = exp(s - max) / sum
// ---------------------------------------------------------------------------
__global__ __launch_bounds__(256) void normalize_kernel(float* __restrict__ attn)
{
    int idx = blockIdx.x * 256 + threadIdx.x;   // float4 index, < 8388608
    int row = idx >> 10;                        // IN_LEN/4 = 1024 float4 per row
    float m   = g_rowmax[row];
    float inv = 1.0f / g_rowsum[row];
    float4 v = ((const float4*)attn)[idx];
    v.x = __expf(v.x - m) * inv;
    v.y = __expf(v.y - m) * inv;
    v.z = __expf(v.z - m) * inv;
    v.w = __expf(v.w - m) * inv;
    ((float4*)attn)[idx] = v;
}

// ---------------------------------------------------------------------------
// GEMM2: context[b,o,h] = sum_i P[b,o,i] * V[b,i,h]  (A @ B, B is K-by-N row-major)
// 128x128 tile, BK=16, 256 threads, 8x8 per thread.
// ---------------------------------------------------------------------------
__global__ __launch_bounds__(256) void gemm2_kernel(
    const float* __restrict__ P, const float* __restrict__ V, float* __restrict__ C)
{
    int b  = blockIdx.z;
    int m0 = blockIdx.y * 128;   // out rows
    int n0 = blockIdx.x * 128;   // h cols
    const float* A  = P + (size_t)b * OUT_LEN * IN_LEN;
    const float* Bm = V + (size_t)b * IN_LEN  * HDIM;

    __shared__ float As[16][128];
    __shared__ float Bs[16][128];

    int tid = threadIdx.x;
    int tx = tid & 15, ty = tid >> 4;

    float acc[8][8] = {};

    for (int k0 = 0; k0 < IN_LEN; k0 += 16) {
#pragma unroll
        for (int s = 0; s < 2; s++) {
            int f   = tid + s * 256;
            int row = f >> 2;
            int kq  = (f & 3) << 2;
            float4 v = *reinterpret_cast<const float4*>(&A[(size_t)(m0 + row) * IN_LEN + k0 + kq]);
            As[kq + 0][row] = v.x; As[kq + 1][row] = v.y;
            As[kq + 2][row] = v.z; As[kq + 3][row] = v.w;
            int kr = f >> 5;            // 0..15
            int nq = (f & 31) << 2;     // 0..124
            *(float4*)&Bs[kr][nq] =
                *reinterpret_cast<const float4*>(&Bm[(size_t)(k0 + kr) * HDIM + n0 + nq]);
        }
        __syncthreads();
#pragma unroll
        for (int kk = 0; kk < 16; kk++) {
            float a[8], bb[8];
            *(float4*)&a[0]  = *(float4*)&As[kk][ty * 8];
            *(float4*)&a[4]  = *(float4*)&As[kk][ty * 8 + 4];
            *(float4*)&bb[0] = *(float4*)&Bs[kk][tx * 8];
            *(float4*)&bb[4] = *(float4*)&Bs[kk][tx * 8 + 4];
#pragma unroll
            for (int i = 0; i < 8; i++)
#pragma unroll
                for (int j = 0; j < 8; j++)
                    acc[i][j] = fmaf(a[i], bb[j], acc[i][j]);
        }
        __syncthreads();
    }

#pragma unroll
    for (int i = 0; i < 8; i++) {
        int m = m0 + ty * 8 + i;
        float4* dst = (float4*)&C[((size_t)b * OUT_LEN + m) * HDIM + n0 + tx * 8];
        dst[0] = make_float4(acc[i][0], acc[i][1], acc[i][2], acc[i][3]);
        dst[1] = make_float4(acc[i][4], acc[i][5], acc[i][6], acc[i][7]);
    }
}

extern "C" void kernel_launch(void* const* d_in, const int* in_sizes, int n_in,
                              void* d_out, int out_size)
{
    const float* Q       = (const float*)d_in[0];   // output  [B, OUT_LEN, H]
    const float* E       = (const float*)d_in[1];   // encoder [B, IN_LEN, H]
    const int*   lengths = (const int*)  d_in[2];   // [B]

    float* ctx  = (float*)d_out;                             // [B, OUT_LEN, H]
    float* attn = ctx + (size_t)BATCH * OUT_LEN * HDIM;      // [B, OUT_LEN, IN_LEN]

    init_rowmax_kernel<<<NROWS / 256, 256>>>();

    dim3 g1(IN_LEN / 128, OUT_LEN / 128, BATCH);   // (32, 8, 8)
    score_kernel<<<g1, 256>>>(Q, E, lengths, attn);

    rowsum_kernel<<<NROWS, 256>>>(attn);

    int n4 = BATCH * OUT_LEN * IN_LEN / 4;         // 8388608 float4
    normalize_kernel<<<n4 / 256, 256>>>(attn);

    dim3 g2(HDIM / 128, OUT_LEN / 128, BATCH);     // (2, 8, 8)
    gemm2_kernel<<<g2, 256>>>(attn, E, ctx);
}